// round 14
// baseline (speedup 1.0000x reference)
#include <cuda_runtime.h>
#include <cuda_fp16.h>
#include <math.h>
#include <stdint.h>

#define TT 8192
#define DD 1024
#define HH 2048
#define EE 8
#define PAD 256   // row padding so out-of-segment tile rows stay in-bounds

// ---------------- scratch (device globals: allocation-free) ----------------
__device__ int   g_expert[TT];
__device__ int   g_pos[TT];
__device__ float g_prob[TT];
__device__ int   g_counts[EE];
__device__ int   g_off[EE + 1];
__device__ int   g_perm[TT + PAD];

__device__ __half g_Xh[TT * DD];        // fp16 tokens, UNPERMUTED (by token id)
__device__ __half g_Hh[(TT + PAD) * HH];
__device__ __half g_W1h[EE * DD * HH];  // W1 native [E][D][H], fp16
__device__ __half g_W2h[EE * HH * DD];  // W2 native [E][H][D], fp16

// ---------------- PTX helpers (plain compute_103-safe: sm_80-era ops only) ----
__device__ __forceinline__ uint32_t smem_u32(const void* p) {
    uint32_t a;
    asm("{ .reg .u64 t; cvta.to.shared.u64 t, %1; cvt.u32.u64 %0, t; }" : "=r"(a) : "l"(p));
    return a;
}
__device__ __forceinline__ void cp16(uint32_t dst, const void* src) {
    asm volatile("cp.async.cg.shared.global [%0], [%1], 16;" :: "r"(dst), "l"(src) : "memory");
}
__device__ __forceinline__ void cp_commit() { asm volatile("cp.async.commit_group;" ::: "memory"); }
__device__ __forceinline__ void cp_wait1()  { asm volatile("cp.async.wait_group 1;" ::: "memory"); }

#define LDSM4(r0, r1, r2, r3, addr) \
    asm volatile("ldmatrix.sync.aligned.m8n8.x4.shared.b16 {%0,%1,%2,%3}, [%4];" \
        : "=r"(r0), "=r"(r1), "=r"(r2), "=r"(r3) : "r"(addr))

#define LDSM4T(r0, r1, r2, r3, addr) \
    asm volatile("ldmatrix.sync.aligned.m8n8.x4.trans.shared.b16 {%0,%1,%2,%3}, [%4];" \
        : "=r"(r0), "=r"(r1), "=r"(r2), "=r"(r3) : "r"(addr))

#define MMA16816(d, a, b0v, b1v) \
    asm volatile("mma.sync.aligned.m16n8k16.row.col.f32.f16.f16.f32 " \
        "{%0,%1,%2,%3}, {%4,%5,%6,%7}, {%8,%9}, {%0,%1,%2,%3};" \
        : "+f"((d)[0]), "+f"((d)[1]), "+f"((d)[2]), "+f"((d)[3]) \
        : "r"((a)[0]), "r"((a)[1]), "r"((a)[2]), "r"((a)[3]), "r"(b0v), "r"(b1v))

// ---------------- tiny setup kernels ----------------
__global__ void zero_counts_kernel() {
    if (threadIdx.x < EE) g_counts[threadIdx.x] = 0;
}

// fp32 -> fp16 convert of 8 contiguous elems at element index i8
__device__ __forceinline__ void conv8(const float* __restrict__ W,
                                      __half* __restrict__ T, size_t i8) {
    const float4* s = (const float4*)(W + i8);
    float4 v0 = s[0], v1 = s[1];
    __half2 a2, b2, c2, d2;
    a2.x = __float2half_rn(v0.x); a2.y = __float2half_rn(v0.y);
    b2.x = __float2half_rn(v0.z); b2.y = __float2half_rn(v0.w);
    c2.x = __float2half_rn(v1.x); c2.y = __float2half_rn(v1.y);
    d2.x = __float2half_rn(v1.z); d2.y = __float2half_rn(v1.w);
    uint4 o;
    o.x = *(uint32_t*)&a2; o.y = *(uint32_t*)&b2;
    o.z = *(uint32_t*)&c2; o.w = *(uint32_t*)&d2;
    *(uint4*)(T + i8) = o;
}

// Fused launch: blocks [0,1024)            = fp32 router (Wr in smem, exact)
//               blocks [1024, 1024+4096)   = x fp32->fp16 convert (unpermuted)
//               blocks [5120, 5120+8192)   = W1 fp32->fp16 convert
__global__ void router_wconv_kernel(const float* __restrict__ x,
                                    const float* __restrict__ Wr,
                                    const float* __restrict__ br,
                                    const float* __restrict__ W1,
                                    __half* __restrict__ Xh,
                                    __half* __restrict__ T1) {
    int b = blockIdx.x;
    if (b < TT / 8) {
        // ---- router: stage Wr (32 KB) in smem once per block ----
        __shared__ float sWr[DD * EE];
        for (int i = threadIdx.x; i < DD * EE / 4; i += 256)
            ((float4*)sWr)[i] = ((const float4*)Wr)[i];
        __syncthreads();

        int token = b * 8 + (threadIdx.x >> 5);
        int lane  = threadIdx.x & 31;
        const float* xr = x + (size_t)token * DD;
        float acc[EE];
#pragma unroll
        for (int e = 0; e < EE; e++) acc[e] = 0.f;
        for (int d = lane; d < DD; d += 32) {
            float xv = xr[d];
            const float4* w = (const float4*)(sWr + d * EE);
            float4 w0 = w[0], w1 = w[1];
            acc[0] += xv * w0.x; acc[1] += xv * w0.y;
            acc[2] += xv * w0.z; acc[3] += xv * w0.w;
            acc[4] += xv * w1.x; acc[5] += xv * w1.y;
            acc[6] += xv * w1.z; acc[7] += xv * w1.w;
        }
#pragma unroll
        for (int e = 0; e < EE; e++) {
#pragma unroll
            for (int o = 16; o; o >>= 1) acc[e] += __shfl_xor_sync(0xffffffffu, acc[e], o);
        }
        if (lane == 0) {
            float m = -1e30f; int best = 0;
#pragma unroll
            for (int e = 0; e < EE; e++) {
                float l = acc[e] + br[e];
                acc[e] = l;
                if (l > m) { m = l; best = e; }
            }
            float s = 0.f;
#pragma unroll
            for (int e = 0; e < EE; e++) s += expf(acc[e] - m);
            g_expert[token] = best;
            g_prob[token]   = 1.f / s;
            g_pos[token]    = atomicAdd(&g_counts[best], 1);
        }
    } else if (b < TT / 8 + 4096) {
        // ---- x convert: 4096 blocks x 256 thr x 8 elems = 8.4M elems ----
        int wb = b - TT / 8;
        size_t i8 = (((size_t)wb * 256) + threadIdx.x) * 8;
        conv8(x, Xh, i8);
    } else {
        // ---- W1 convert: 8192 blocks x 256 thr x 8 elems = 16.8M elems ----
        int wb = b - TT / 8 - 4096;
        size_t i8 = (((size_t)wb * 256) + threadIdx.x) * 8;
        conv8(W1, T1, i8);
    }
}

// one block: prefix-sum counts, then scatter-fill perm (+ guard padding)
__global__ void scan_perm_kernel() {
    __shared__ int soff[EE];
    if (threadIdx.x == 0) {
        int s = 0;
#pragma unroll
        for (int e = 0; e < EE; e++) { g_off[e] = s; soff[e] = s; s += g_counts[e]; }
        g_off[EE] = s;
    }
    __syncthreads();
    for (int t = threadIdx.x; t < TT; t += blockDim.x) {
        int dst = soff[g_expert[t]] + g_pos[t];
        g_perm[dst] = t;
    }
    for (int t = TT + threadIdx.x; t < TT + PAD; t += blockDim.x)
        g_perm[t] = 0;
}

// ---------------- grouped fp16 HMMA GEMM, 3-stage ring, 3 CTAs/SM -----------
// Block tile 64(M) x 128(N), BK=64. 8 warps (256 thr) in 2(M) x 4(N); each
// warp computes 32x32. acc=32 regs/thread -> ~80 regs -> 3 CTAs/SM (24 warps).
// A (FIRST): unpermuted Xh read INDIRECTLY via g_perm (no gather pass).
// A (!FIRST): Hh in segment order, direct.
// B: native [K][NOUT]; smem tile [64 x 256B], trans ldmatrix.
// FIRST kernel carries an extra z-plane (blockIdx.z == EE) that stream-converts
// W2 fp32->fp16 in GEMM1's wave tail.
static constexpr int BM = 64, BN = 128, BK = 64;
static constexpr int NTHR = 256;
static constexpr int A_T = BM * 128;                    // 8 KB A tile
static constexpr int B_T = BK * 256;                    // 16 KB B tile
static constexpr int STAGE = A_T + B_T;                 // 24 KB
static constexpr int SMEM_GEMM = 3 * STAGE;             // 72 KB -> 3 CTAs/SM

template <int K, int NOUT, bool FIRST>
__global__ void __launch_bounds__(NTHR, 3) gemm_mma(
    const __half* __restrict__ A,
    const __half* __restrict__ B_all,
    const float* __restrict__ ball,
    __half* __restrict__ OutH,
    float* __restrict__ OutF,
    const float* __restrict__ W2src,
    __half* __restrict__ W2dst)
{
    constexpr int KC = K / BK;

    if (FIRST && blockIdx.z == EE) {
        // ---- W2 convert plane: 2048 blocks x 256 thr x 4 iters x 8 elems ----
        int bid = blockIdx.x + (int)gridDim.x * blockIdx.y;   // 0..2047
        size_t base = ((size_t)bid * NTHR + threadIdx.x) * 8;
#pragma unroll
        for (int it = 0; it < 4; it++)
            conv8(W2src, W2dst, base + (size_t)it * ((size_t)2048 * NTHR * 8));
        return;
    }

    int e = blockIdx.z;
    int rowBeg = g_off[e], rowEnd = g_off[e + 1];
    int row0 = rowBeg + blockIdx.y * BM;
    if (row0 >= rowEnd) return;
    int n0 = blockIdx.x * BN;

    const __half* BE = B_all + (size_t)e * K * NOUT;
    const float* bias = ball + (size_t)e * NOUT;

    extern __shared__ __align__(128) char smem[];
    uint32_t sb = smem_u32(smem);

    int tid = threadIdx.x;
    int wid = tid >> 5, lane = tid & 31;
    int warpM = wid & 1, warpN = wid >> 1;              // 2 x 4

    // ---- per-thread gmem->smem geometry (chunk-invariant) ----
    // A tile: 512 chunks of 16B over [64 rows][8 chunks] -> 2 per thread.
    uint32_t smoA[2];
    const __half* ApB[2];
#pragma unroll
    for (int j = 0; j < 2; j++) {
        int id = tid + j * NTHR;
        int r = id >> 3, c = id & 7;
        smoA[j] = (uint32_t)(r * 128 + ((c ^ (r & 7)) << 4));
        int grow = row0 + r;                 // < TT + PAD by construction
        size_t rowBase;
        if (FIRST) rowBase = (size_t)g_perm[grow] * K;
        else       rowBase = (size_t)grow * K;
        ApB[j] = A + rowBase + c * 8;
    }
    // B tile: 1024 chunks of 16B over [64 rows][16 chunks] -> 4 per thread
    uint32_t smoB[4]; int rkB[4];
#pragma unroll
    for (int j = 0; j < 4; j++) {
        int id = tid + j * NTHR;
        int r = id >> 4, c = id & 15;
        smoB[j] = (uint32_t)(r * 256 + ((c ^ (r & 7)) << 4));
        rkB[j] = r * NOUT + c * 8;
    }

    // ---- ldmatrix per-thread geometry ----
    int rA  = warpM * 32 + (lane & 15);
    int cxA = lane >> 4;
    int sAx = rA & 7;
    // B (trans): lanes 0-7 k0-7, 8-15 k8-15, 16-23 k0-7(+n8), 24-31 k8-15(+n8)
    int bRow = (lane & 7) + (((lane >> 3) & 1) << 3);   // 0..15
    uint32_t bByte = (uint32_t)bRow * 256;
    int c16b = warpN * 4 + (lane >> 4);                 // +2*j per n16-tile
    int sBx = lane & 7;

    float acc[2][4][4];
#pragma unroll
    for (int i = 0; i < 2; i++)
#pragma unroll
        for (int j = 0; j < 4; j++)
#pragma unroll
            for (int q = 0; q < 4; q++) acc[i][j][q] = 0.f;

    auto issue = [&](int cn) {
        if (cn < KC) {
            int kk = cn * BK;
            uint32_t st = sb + (uint32_t)((cn % 3) * STAGE);
            const __half* Bp = BE + (size_t)kk * NOUT + n0;
#pragma unroll
            for (int j = 0; j < 2; j++) cp16(st + smoA[j], ApB[j] + kk);
#pragma unroll
            for (int j = 0; j < 4; j++) cp16(st + A_T + smoB[j], Bp + rkB[j]);
        }
        cp_commit();   // uniform group count even in the tail
    };

    issue(0); issue(1);

    for (int c = 0; c < KC; c++) {
        cp_wait1();                    // stage c complete (c+1 may be pending)
        __syncthreads();               // all warps done with stage c-1
        issue(c + 2);                  // overwrites stage c-1's buffer
        uint32_t st = sb + (uint32_t)((c % 3) * STAGE);
        uint32_t aSm = st, bSm = st + A_T;
#pragma unroll
        for (int ks = 0; ks < 4; ks++) {
            uint32_t aro = (uint32_t)((((ks << 1) + cxA) ^ sAx) << 4);
            uint32_t af[2][4];
#pragma unroll
            for (int i = 0; i < 2; i++) {
                uint32_t roff = (uint32_t)((rA + i * 16) * 128) + aro;
                LDSM4(af[i][0], af[i][1], af[i][2], af[i][3], aSm + roff);
            }
            uint32_t bf[2][4];
            uint32_t bks = bSm + (uint32_t)(ks * 4096) + bByte;
#pragma unroll
            for (int j = 0; j < 2; j++) {
                uint32_t addr = bks + (uint32_t)(((c16b + 2 * j) ^ sBx) << 4);
                LDSM4T(bf[j][0], bf[j][1], bf[j][2], bf[j][3], addr);
            }
#pragma unroll
            for (int i = 0; i < 2; i++)
#pragma unroll
                for (int j = 0; j < 2; j++) {
                    MMA16816(acc[i][2 * j],     af[i], bf[j][0], bf[j][1]);
                    MMA16816(acc[i][2 * j + 1], af[i], bf[j][2], bf[j][3]);
                }
        }
    }

    // ---- epilogue ----
    int mb = row0 + warpM * 32;
    int nb = n0 + warpN * 32;
    int lr = lane >> 2, lc = (lane & 3) * 2;
    float2 blv[4];
#pragma unroll
    for (int j = 0; j < 4; j++) {
        int col = nb + j * 8 + lc;
        blv[j].x = __ldg(bias + col);
        blv[j].y = __ldg(bias + col + 1);
    }
#pragma unroll
    for (int i = 0; i < 2; i++) {
#pragma unroll
        for (int h = 0; h < 2; h++) {
            int row = mb + i * 16 + lr + h * 8;
            if (row < rowEnd) {
                if (FIRST) {
                    uint32_t* dh = (uint32_t*)(OutH + (size_t)row * NOUT);
#pragma unroll
                    for (int j = 0; j < 4; j++) {
                        int col = nb + j * 8 + lc;
                        float v0 = acc[i][j][2 * h]     + blv[j].x;
                        float v1 = acc[i][j][2 * h + 1] + blv[j].y;
                        v0 = fmaxf(v0, 0.f); v1 = fmaxf(v1, 0.f);
                        __half2 hh;
                        hh.x = __float2half_rn(v0); hh.y = __float2half_rn(v1);
                        dh[col >> 1] = *(uint32_t*)&hh;
                    }
                } else {
                    int tok = g_perm[row];
                    float p = g_prob[tok];
                    float2* dst = (float2*)(OutF + (size_t)tok * NOUT);
#pragma unroll
                    for (int j = 0; j < 4; j++) {
                        int col = nb + j * 8 + lc;
                        float2 o;
                        o.x = (acc[i][j][2 * h]     + blv[j].x) * p;
                        o.y = (acc[i][j][2 * h + 1] + blv[j].y) * p;
                        dst[col >> 1] = o;
                    }
                }
            }
        }
    }
}

// ---------------- entry ----------------
extern "C" void kernel_launch(void* const* d_in, const int* in_sizes, int n_in,
                              void* d_out, int out_size) {
    const float* x  = (const float*)d_in[0];
    const float* Wr = (const float*)d_in[1];
    const float* br = (const float*)d_in[2];
    const float* W1 = (const float*)d_in[3];
    const float* b1 = (const float*)d_in[4];
    const float* W2 = (const float*)d_in[5];
    const float* b2 = (const float*)d_in[6];
    float* out = (float*)d_out;

    __half *Xh, *Hh, *W1h, *W2h;
    cudaGetSymbolAddress((void**)&Xh, g_Xh);
    cudaGetSymbolAddress((void**)&Hh, g_Hh);
    cudaGetSymbolAddress((void**)&W1h, g_W1h);
    cudaGetSymbolAddress((void**)&W2h, g_W2h);

    cudaFuncSetAttribute(gemm_mma<DD, HH, true>,  cudaFuncAttributeMaxDynamicSharedMemorySize, SMEM_GEMM);
    cudaFuncSetAttribute(gemm_mma<HH, DD, false>, cudaFuncAttributeMaxDynamicSharedMemorySize, SMEM_GEMM);

    zero_counts_kernel<<<1, 32>>>();
    // router (1024) + x-convert (4096) + W1-convert (8192): one launch
    router_wconv_kernel<<<TT / 8 + 4096 + 8192, 256>>>(x, Wr, br, W1, Xh, W1h);
    scan_perm_kernel<<<1, 1024>>>();

    // GEMM1 (perm-indirect A) + trailing W2-convert plane (z == EE)
    dim3 g1(HH / BN, TT / BM, EE + 1);
    gemm_mma<DD, HH, true><<<g1, NTHR, SMEM_GEMM>>>(Xh, W1h, b1, Hh, nullptr, W2, W2h);
    dim3 g2(DD / BN, TT / BM, EE);
    gemm_mma<HH, DD, false><<<g2, NTHR, SMEM_GEMM>>>(Hh, W2h, b2, nullptr, out, nullptr, nullptr);
}

// round 15
// speedup vs baseline: 1.0833x; 1.0833x over previous
#include <cuda_runtime.h>
#include <cuda_fp16.h>
#include <math.h>
#include <stdint.h>

#define TT 8192
#define DD 1024
#define HH 2048
#define EE 8
#define PAD 256   // row padding so out-of-segment tile rows stay in-bounds

// ---------------- scratch (device globals: allocation-free) ----------------
__device__ int   g_expert[TT];
__device__ int   g_pos[TT];
__device__ float g_prob[TT];
__device__ int   g_counts[EE];          // zero at load; re-zeroed by scan_perm
__device__ int   g_off[EE + 1];
__device__ int   g_perm[TT + PAD];

__device__ __half g_Xh[TT * DD];        // fp16 tokens, UNPERMUTED (by token id)
__device__ __half g_Hh[(TT + PAD) * HH];
__device__ __half g_W1h[EE * DD * HH];  // W1 native [E][D][H], fp16
__device__ __half g_W2h[EE * HH * DD];  // W2 native [E][H][D], fp16

// ---------------- PTX helpers (plain compute_103-safe: sm_80-era ops only) ----
__device__ __forceinline__ uint32_t smem_u32(const void* p) {
    uint32_t a;
    asm("{ .reg .u64 t; cvta.to.shared.u64 t, %1; cvt.u32.u64 %0, t; }" : "=r"(a) : "l"(p));
    return a;
}
__device__ __forceinline__ void cp16(uint32_t dst, const void* src) {
    asm volatile("cp.async.cg.shared.global [%0], [%1], 16;" :: "r"(dst), "l"(src) : "memory");
}
__device__ __forceinline__ void cp_commit() { asm volatile("cp.async.commit_group;" ::: "memory"); }
__device__ __forceinline__ void cp_wait1()  { asm volatile("cp.async.wait_group 1;" ::: "memory"); }

#define LDSM4(r0, r1, r2, r3, addr) \
    asm volatile("ldmatrix.sync.aligned.m8n8.x4.shared.b16 {%0,%1,%2,%3}, [%4];" \
        : "=r"(r0), "=r"(r1), "=r"(r2), "=r"(r3) : "r"(addr))

#define LDSM4T(r0, r1, r2, r3, addr) \
    asm volatile("ldmatrix.sync.aligned.m8n8.x4.trans.shared.b16 {%0,%1,%2,%3}, [%4];" \
        : "=r"(r0), "=r"(r1), "=r"(r2), "=r"(r3) : "r"(addr))

#define MMA16816(d, a, b0v, b1v) \
    asm volatile("mma.sync.aligned.m16n8k16.row.col.f32.f16.f16.f32 " \
        "{%0,%1,%2,%3}, {%4,%5,%6,%7}, {%8,%9}, {%0,%1,%2,%3};" \
        : "+f"((d)[0]), "+f"((d)[1]), "+f"((d)[2]), "+f"((d)[3]) \
        : "r"((a)[0]), "r"((a)[1]), "r"((a)[2]), "r"((a)[3]), "r"(b0v), "r"(b1v))

// ---------------- small kernels ----------------
// fp32 -> fp16 convert of 8 contiguous elems at element index i8
__device__ __forceinline__ void conv8(const float* __restrict__ W,
                                      __half* __restrict__ T, size_t i8) {
    const float4* s = (const float4*)(W + i8);
    float4 v0 = s[0], v1 = s[1];
    __half2 a2, b2, c2, d2;
    a2.x = __float2half_rn(v0.x); a2.y = __float2half_rn(v0.y);
    b2.x = __float2half_rn(v0.z); b2.y = __float2half_rn(v0.w);
    c2.x = __float2half_rn(v1.x); c2.y = __float2half_rn(v1.y);
    d2.x = __float2half_rn(v1.z); d2.y = __float2half_rn(v1.w);
    uint4 o;
    o.x = *(uint32_t*)&a2; o.y = *(uint32_t*)&b2;
    o.z = *(uint32_t*)&c2; o.w = *(uint32_t*)&d2;
    *(uint4*)(T + i8) = o;
}

// Fused launch: blocks [0,1024)          = fp32 router (Wr in smem, exact) which
//                                          ALSO emits Xh = fp16(x) as it reads x
//               blocks [1024,1024+8192)  = W1 fp32->fp16 convert
__global__ void router_wconv_kernel(const float* __restrict__ x,
                                    const float* __restrict__ Wr,
                                    const float* __restrict__ br,
                                    const float* __restrict__ W1,
                                    __half* __restrict__ Xh,
                                    __half* __restrict__ T1) {
    int b = blockIdx.x;
    if (b < TT / 8) {
        // ---- router: stage Wr (32 KB) in smem once per block ----
        __shared__ float sWr[DD * EE];
        for (int i = threadIdx.x; i < DD * EE / 4; i += 256)
            ((float4*)sWr)[i] = ((const float4*)Wr)[i];
        __syncthreads();

        int token = b * 8 + (threadIdx.x >> 5);
        int lane  = threadIdx.x & 31;
        const float* xr = x + (size_t)token * DD;
        __half* xh = Xh + (size_t)token * DD;
        float acc[EE];
#pragma unroll
        for (int e = 0; e < EE; e++) acc[e] = 0.f;
        for (int d = lane; d < DD; d += 32) {
            float xv = xr[d];
            xh[d] = __float2half_rn(xv);          // fused x->fp16 emit
            const float4* w = (const float4*)(sWr + d * EE);
            float4 w0 = w[0], w1 = w[1];
            acc[0] += xv * w0.x; acc[1] += xv * w0.y;
            acc[2] += xv * w0.z; acc[3] += xv * w0.w;
            acc[4] += xv * w1.x; acc[5] += xv * w1.y;
            acc[6] += xv * w1.z; acc[7] += xv * w1.w;
        }
#pragma unroll
        for (int e = 0; e < EE; e++) {
#pragma unroll
            for (int o = 16; o; o >>= 1) acc[e] += __shfl_xor_sync(0xffffffffu, acc[e], o);
        }
        if (lane == 0) {
            float m = -1e30f; int best = 0;
#pragma unroll
            for (int e = 0; e < EE; e++) {
                float l = acc[e] + br[e];
                acc[e] = l;
                if (l > m) { m = l; best = e; }
            }
            float s = 0.f;
#pragma unroll
            for (int e = 0; e < EE; e++) s += expf(acc[e] - m);
            g_expert[token] = best;
            g_prob[token]   = 1.f / s;
            g_pos[token]    = atomicAdd(&g_counts[best], 1);
        }
    } else {
        // ---- W1 convert: 8192 blocks x 256 thr x 8 elems = 16.8M elems ----
        int wb = b - TT / 8;
        size_t i8 = (((size_t)wb * 256) + threadIdx.x) * 8;
        conv8(W1, T1, i8);
    }
}

// one block: prefix-sum counts, scatter-fill perm (+ guard), re-zero counts
__global__ void scan_perm_kernel() {
    __shared__ int soff[EE];
    if (threadIdx.x == 0) {
        int s = 0;
#pragma unroll
        for (int e = 0; e < EE; e++) { g_off[e] = s; soff[e] = s; s += g_counts[e]; }
        g_off[EE] = s;
    }
    __syncthreads();
    if (threadIdx.x < EE) g_counts[threadIdx.x] = 0;   // ready for next replay
    for (int t = threadIdx.x; t < TT; t += blockDim.x) {
        int dst = soff[g_expert[t]] + g_pos[t];
        g_perm[dst] = t;
    }
    for (int t = TT + threadIdx.x; t < TT + PAD; t += blockDim.x)
        g_perm[t] = 0;
}

// ---------------- grouped fp16 HMMA GEMM, 3-stage ring, 2 CTAs/SM -----------
// Block tile 128(M) x 128(N), BK=64. 8 warps (256 thr) in 4(M) x 2(N); each
// warp computes 32x64. 2 CTAs/SM: cross-CTA overlap hides barriers/epilogue.
// A (FIRST): unpermuted Xh read INDIRECTLY via g_perm (no gather pass).
// A (!FIRST): Hh in segment order, direct.
// B: native [K][NOUT]; smem tile [64 x 256B], trans ldmatrix.
// FIRST kernel carries an extra z-plane (blockIdx.z == EE) that stream-converts
// W2 fp32->fp16 in GEMM1's wave tail.
static constexpr int BM = 128, BN = 128, BK = 64;
static constexpr int NTHR = 256;
static constexpr int A_T = BM * 128;                    // 16 KB A tile
static constexpr int B_T = BK * 256;                    // 16 KB B tile
static constexpr int STAGE = A_T + B_T;                 // 32 KB
static constexpr int SMEM_GEMM = 3 * STAGE;             // 96 KB -> 2 CTAs/SM

template <int K, int NOUT, bool FIRST>
__global__ void __launch_bounds__(NTHR, 2) gemm_mma(
    const __half* __restrict__ A,
    const __half* __restrict__ B_all,
    const float* __restrict__ ball,
    __half* __restrict__ OutH,
    float* __restrict__ OutF,
    const float* __restrict__ W2src,
    __half* __restrict__ W2dst)
{
    constexpr int KC = K / BK;

    if (FIRST && blockIdx.z == EE) {
        // ---- W2 convert plane: 1024 blocks x 256 thr x 8 iters x 8 elems ----
        int bid = blockIdx.x + (int)gridDim.x * blockIdx.y;   // 0..1023
        size_t base = ((size_t)bid * NTHR + threadIdx.x) * 8;
#pragma unroll
        for (int it = 0; it < 8; it++)
            conv8(W2src, W2dst, base + (size_t)it * ((size_t)1024 * NTHR * 8));
        return;
    }

    int e = blockIdx.z;
    int rowBeg = g_off[e], rowEnd = g_off[e + 1];
    int row0 = rowBeg + blockIdx.y * BM;
    if (row0 >= rowEnd) return;
    int n0 = blockIdx.x * BN;

    const __half* BE = B_all + (size_t)e * K * NOUT;
    const float* bias = ball + (size_t)e * NOUT;

    extern __shared__ __align__(128) char smem[];
    uint32_t sb = smem_u32(smem);

    int tid = threadIdx.x;
    int wid = tid >> 5, lane = tid & 31;
    int warpM = wid & 3, warpN = wid >> 2;              // 4 x 2

    // ---- per-thread gmem->smem geometry (chunk-invariant) ----
    // A tile: 1024 chunks of 16B over [128 rows][8 chunks] -> 4 per thread.
    // Resolve each owned row's base pointer once (indirect for FIRST).
    uint32_t smoA[4];
    const __half* ApB[4];
#pragma unroll
    for (int j = 0; j < 4; j++) {
        int id = tid + j * NTHR;
        int r = id >> 3, c = id & 7;
        smoA[j] = (uint32_t)(r * 128 + ((c ^ (r & 7)) << 4));
        int grow = row0 + r;                 // < TT + PAD by construction
        size_t rowBase;
        if (FIRST) rowBase = (size_t)g_perm[grow] * K;
        else       rowBase = (size_t)grow * K;
        ApB[j] = A + rowBase + c * 8;
    }
    // B tile: 1024 chunks of 16B over [64 rows][16 chunks] -> 4 per thread
    uint32_t smoB[4]; int rkB[4];
#pragma unroll
    for (int j = 0; j < 4; j++) {
        int id = tid + j * NTHR;
        int r = id >> 4, c = id & 15;
        smoB[j] = (uint32_t)(r * 256 + ((c ^ (r & 7)) << 4));
        rkB[j] = r * NOUT + c * 8;
    }

    // ---- ldmatrix per-thread geometry ----
    int rA  = warpM * 32 + (lane & 15);
    int cxA = lane >> 4;
    int sAx = rA & 7;
    // B (trans): lanes 0-7 k0-7, 8-15 k8-15, 16-23 k0-7(+n8), 24-31 k8-15(+n8)
    int bRow = (lane & 7) + (((lane >> 3) & 1) << 3);   // 0..15
    uint32_t bByte = (uint32_t)bRow * 256;
    int c16b = warpN * 8 + (lane >> 4);                 // +2*j per n16-tile
    int sBx = lane & 7;

    float acc[2][8][4];
#pragma unroll
    for (int i = 0; i < 2; i++)
#pragma unroll
        for (int j = 0; j < 8; j++)
#pragma unroll
            for (int q = 0; q < 4; q++) acc[i][j][q] = 0.f;

    auto issue = [&](int cn) {
        if (cn < KC) {
            int kk = cn * BK;
            uint32_t st = sb + (uint32_t)((cn % 3) * STAGE);
            const __half* Bp = BE + (size_t)kk * NOUT + n0;
#pragma unroll
            for (int j = 0; j < 4; j++) cp16(st + smoA[j], ApB[j] + kk);
#pragma unroll
            for (int j = 0; j < 4; j++) cp16(st + A_T + smoB[j], Bp + rkB[j]);
        }
        cp_commit();   // uniform group count even in the tail
    };

    issue(0); issue(1);

    for (int c = 0; c < KC; c++) {
        cp_wait1();                    // stage c complete (c+1 may be pending)
        __syncthreads();               // all warps done with stage c-1
        issue(c + 2);                  // overwrites stage c-1's buffer
        uint32_t st = sb + (uint32_t)((c % 3) * STAGE);
        uint32_t aSm = st, bSm = st + A_T;
#pragma unroll
        for (int ks = 0; ks < 4; ks++) {
            uint32_t aro = (uint32_t)((((ks << 1) + cxA) ^ sAx) << 4);
            uint32_t af[2][4];
#pragma unroll
            for (int i = 0; i < 2; i++) {
                uint32_t roff = (uint32_t)((rA + i * 16) * 128) + aro;
                LDSM4(af[i][0], af[i][1], af[i][2], af[i][3], aSm + roff);
            }
            uint32_t bf[4][4];
            uint32_t bks = bSm + (uint32_t)(ks * 4096) + bByte;
#pragma unroll
            for (int j = 0; j < 4; j++) {
                uint32_t addr = bks + (uint32_t)(((c16b + 2 * j) ^ sBx) << 4);
                LDSM4T(bf[j][0], bf[j][1], bf[j][2], bf[j][3], addr);
            }
#pragma unroll
            for (int i = 0; i < 2; i++)
#pragma unroll
                for (int j = 0; j < 4; j++) {
                    MMA16816(acc[i][2 * j],     af[i], bf[j][0], bf[j][1]);
                    MMA16816(acc[i][2 * j + 1], af[i], bf[j][2], bf[j][3]);
                }
        }
    }

    // ---- epilogue ----
    int mb = row0 + warpM * 32;
    int nb = n0 + warpN * 64;
    int lr = lane >> 2, lc = (lane & 3) * 2;
    float2 blv[8];
#pragma unroll
    for (int j = 0; j < 8; j++) {
        int col = nb + j * 8 + lc;
        blv[j].x = __ldg(bias + col);
        blv[j].y = __ldg(bias + col + 1);
    }
#pragma unroll
    for (int i = 0; i < 2; i++) {
#pragma unroll
        for (int h = 0; h < 2; h++) {
            int row = mb + i * 16 + lr + h * 8;
            if (row < rowEnd) {
                if (FIRST) {
                    uint32_t* dh = (uint32_t*)(OutH + (size_t)row * NOUT);
#pragma unroll
                    for (int j = 0; j < 8; j++) {
                        int col = nb + j * 8 + lc;
                        float v0 = acc[i][j][2 * h]     + blv[j].x;
                        float v1 = acc[i][j][2 * h + 1] + blv[j].y;
                        v0 = fmaxf(v0, 0.f); v1 = fmaxf(v1, 0.f);
                        __half2 hh;
                        hh.x = __float2half_rn(v0); hh.y = __float2half_rn(v1);
                        dh[col >> 1] = *(uint32_t*)&hh;
                    }
                } else {
                    int tok = g_perm[row];
                    float p = g_prob[tok];
                    float2* dst = (float2*)(OutF + (size_t)tok * NOUT);
#pragma unroll
                    for (int j = 0; j < 8; j++) {
                        int col = nb + j * 8 + lc;
                        float2 o;
                        o.x = (acc[i][j][2 * h]     + blv[j].x) * p;
                        o.y = (acc[i][j][2 * h + 1] + blv[j].y) * p;
                        dst[col >> 1] = o;
                    }
                }
            }
        }
    }
}

// ---------------- entry ----------------
extern "C" void kernel_launch(void* const* d_in, const int* in_sizes, int n_in,
                              void* d_out, int out_size) {
    const float* x  = (const float*)d_in[0];
    const float* Wr = (const float*)d_in[1];
    const float* br = (const float*)d_in[2];
    const float* W1 = (const float*)d_in[3];
    const float* b1 = (const float*)d_in[4];
    const float* W2 = (const float*)d_in[5];
    const float* b2 = (const float*)d_in[6];
    float* out = (float*)d_out;

    __half *Xh, *Hh, *W1h, *W2h;
    cudaGetSymbolAddress((void**)&Xh, g_Xh);
    cudaGetSymbolAddress((void**)&Hh, g_Hh);
    cudaGetSymbolAddress((void**)&W1h, g_W1h);
    cudaGetSymbolAddress((void**)&W2h, g_W2h);

    cudaFuncSetAttribute(gemm_mma<DD, HH, true>,  cudaFuncAttributeMaxDynamicSharedMemorySize, SMEM_GEMM);
    cudaFuncSetAttribute(gemm_mma<HH, DD, false>, cudaFuncAttributeMaxDynamicSharedMemorySize, SMEM_GEMM);

    // router (1024, emits Xh) + W1-convert (8192): one launch, no zero kernel
    router_wconv_kernel<<<TT / 8 + 8192, 256>>>(x, Wr, br, W1, Xh, W1h);
    scan_perm_kernel<<<1, 1024>>>();

    // GEMM1 (perm-indirect A) + trailing W2-convert plane (z == EE)
    dim3 g1(HH / BN, TT / BM, EE + 1);
    gemm_mma<DD, HH, true><<<g1, NTHR, SMEM_GEMM>>>(Xh, W1h, b1, Hh, nullptr, W2, W2h);
    dim3 g2(DD / BN, TT / BM, EE);
    gemm_mma<HH, DD, false><<<g2, NTHR, SMEM_GEMM>>>(Hh, W2h, b2, nullptr, out, nullptr, nullptr);
}

// round 16
// speedup vs baseline: 1.0984x; 1.0139x over previous
#include <cuda_runtime.h>
#include <cuda_fp16.h>
#include <math.h>
#include <stdint.h>

#define TT 8192
#define DD 1024
#define HH 2048
#define EE 8
#define PAD 256   // row padding so out-of-segment tile rows stay in-bounds

// ---------------- scratch (device globals: allocation-free) ----------------
__device__ int   g_expert[TT];
__device__ int   g_pos[TT];
__device__ float g_prob[TT];
__device__ int   g_counts[EE];          // zero at load; re-zeroed by scan_perm
__device__ int   g_off[EE + 1];
__device__ int   g_perm[TT + PAD];

__device__ __half g_Xh[TT * DD];        // fp16 tokens, UNPERMUTED (by token id)
__device__ __half g_Hh[(TT + PAD) * HH];
__device__ __half g_W1h[EE * DD * HH];  // W1 native [E][D][H], fp16
__device__ __half g_W2h[EE * HH * DD];  // W2 native [E][H][D], fp16

// ---------------- PTX helpers (plain compute_103-safe: sm_80-era ops only) ----
__device__ __forceinline__ uint32_t smem_u32(const void* p) {
    uint32_t a;
    asm("{ .reg .u64 t; cvta.to.shared.u64 t, %1; cvt.u32.u64 %0, t; }" : "=r"(a) : "l"(p));
    return a;
}
__device__ __forceinline__ void cp16(uint32_t dst, const void* src) {
    asm volatile("cp.async.cg.shared.global [%0], [%1], 16;" :: "r"(dst), "l"(src) : "memory");
}
__device__ __forceinline__ void cp_commit() { asm volatile("cp.async.commit_group;" ::: "memory"); }
__device__ __forceinline__ void cp_wait1()  { asm volatile("cp.async.wait_group 1;" ::: "memory"); }

#define LDSM4(r0, r1, r2, r3, addr) \
    asm volatile("ldmatrix.sync.aligned.m8n8.x4.shared.b16 {%0,%1,%2,%3}, [%4];" \
        : "=r"(r0), "=r"(r1), "=r"(r2), "=r"(r3) : "r"(addr))

#define LDSM4T(r0, r1, r2, r3, addr) \
    asm volatile("ldmatrix.sync.aligned.m8n8.x4.trans.shared.b16 {%0,%1,%2,%3}, [%4];" \
        : "=r"(r0), "=r"(r1), "=r"(r2), "=r"(r3) : "r"(addr))

#define MMA16816(d, a, b0v, b1v) \
    asm volatile("mma.sync.aligned.m16n8k16.row.col.f32.f16.f16.f32 " \
        "{%0,%1,%2,%3}, {%4,%5,%6,%7}, {%8,%9}, {%0,%1,%2,%3};" \
        : "+f"((d)[0]), "+f"((d)[1]), "+f"((d)[2]), "+f"((d)[3]) \
        : "r"((a)[0]), "r"((a)[1]), "r"((a)[2]), "r"((a)[3]), "r"(b0v), "r"(b1v))

// ---------------- small kernels ----------------
// fp32 -> fp16 convert of 8 contiguous elems at element index i8
__device__ __forceinline__ void conv8(const float* __restrict__ W,
                                      __half* __restrict__ T, size_t i8) {
    const float4* s = (const float4*)(W + i8);
    float4 v0 = s[0], v1 = s[1];
    __half2 a2, b2, c2, d2;
    a2.x = __float2half_rn(v0.x); a2.y = __float2half_rn(v0.y);
    b2.x = __float2half_rn(v0.z); b2.y = __float2half_rn(v0.w);
    c2.x = __float2half_rn(v1.x); c2.y = __float2half_rn(v1.y);
    d2.x = __float2half_rn(v1.z); d2.y = __float2half_rn(v1.w);
    uint4 o;
    o.x = *(uint32_t*)&a2; o.y = *(uint32_t*)&b2;
    o.z = *(uint32_t*)&c2; o.w = *(uint32_t*)&d2;
    *(uint4*)(T + i8) = o;
}

// Fused launch (512 thr blocks):
//   blocks [0,512)       = fp32 router (16 tokens/block, Wr in smem, exact),
//                          ALSO emits Xh = fp16(x) as it reads x
//   blocks [512,512+1024) = W1 fp32->fp16 convert (32 elems/thread)
__global__ void router_wconv_kernel(const float* __restrict__ x,
                                    const float* __restrict__ Wr,
                                    const float* __restrict__ br,
                                    const float* __restrict__ W1,
                                    __half* __restrict__ Xh,
                                    __half* __restrict__ T1) {
    int b = blockIdx.x;
    if (b < TT / 16) {
        // ---- router: stage Wr (32 KB) in smem once per block ----
        __shared__ float sWr[DD * EE];
        for (int i = threadIdx.x; i < DD * EE / 4; i += 512)
            ((float4*)sWr)[i] = ((const float4*)Wr)[i];
        __syncthreads();

        int token = b * 16 + (threadIdx.x >> 5);
        int lane  = threadIdx.x & 31;
        const float* xr = x + (size_t)token * DD;
        __half* xh = Xh + (size_t)token * DD;
        float acc[EE];
#pragma unroll
        for (int e = 0; e < EE; e++) acc[e] = 0.f;
        for (int d = lane; d < DD; d += 32) {
            float xv = xr[d];
            xh[d] = __float2half_rn(xv);          // fused x->fp16 emit
            const float4* w = (const float4*)(sWr + d * EE);
            float4 w0 = w[0], w1 = w[1];
            acc[0] += xv * w0.x; acc[1] += xv * w0.y;
            acc[2] += xv * w0.z; acc[3] += xv * w0.w;
            acc[4] += xv * w1.x; acc[5] += xv * w1.y;
            acc[6] += xv * w1.z; acc[7] += xv * w1.w;
        }
#pragma unroll
        for (int e = 0; e < EE; e++) {
#pragma unroll
            for (int o = 16; o; o >>= 1) acc[e] += __shfl_xor_sync(0xffffffffu, acc[e], o);
        }
        if (lane == 0) {
            float m = -1e30f; int best = 0;
#pragma unroll
            for (int e = 0; e < EE; e++) {
                float l = acc[e] + br[e];
                acc[e] = l;
                if (l > m) { m = l; best = e; }
            }
            float s = 0.f;
#pragma unroll
            for (int e = 0; e < EE; e++) s += expf(acc[e] - m);
            g_expert[token] = best;
            g_prob[token]   = 1.f / s;
            g_pos[token]    = atomicAdd(&g_counts[best], 1);
        }
    } else {
        // ---- W1 convert: 1024 blocks x 512 thr x 4 iters x 8 elems ----
        int wb = b - TT / 16;                   // 0..1023
        size_t base = (((size_t)wb * 512) + threadIdx.x) * 8;
#pragma unroll
        for (int it = 0; it < 4; it++)
            conv8(W1, T1, base + (size_t)it * ((size_t)1024 * 512 * 8));
    }
}

// one block: prefix-sum counts, scatter-fill perm (+ guard), re-zero counts
__global__ void scan_perm_kernel() {
    __shared__ int soff[EE];
    if (threadIdx.x == 0) {
        int s = 0;
#pragma unroll
        for (int e = 0; e < EE; e++) { g_off[e] = s; soff[e] = s; s += g_counts[e]; }
        g_off[EE] = s;
    }
    __syncthreads();
    if (threadIdx.x < EE) g_counts[threadIdx.x] = 0;   // ready for next replay
    for (int t = threadIdx.x; t < TT; t += blockDim.x) {
        int dst = soff[g_expert[t]] + g_pos[t];
        g_perm[dst] = t;
    }
    for (int t = TT + threadIdx.x; t < TT + PAD; t += blockDim.x)
        g_perm[t] = 0;
}

// ---------------- grouped fp16 HMMA GEMM, 3-stage ring, 2 CTAs/SM -----------
// Block tile 128(M) x 128(N), BK=64. 8 warps (256 thr) in 4(M) x 2(N); each
// warp computes 32x64. Prefetch cp.asyncs are interleaved into the ks loop
// (2 per ks) so fragment LDSMs issue immediately after the barrier.
// A (FIRST): unpermuted Xh read INDIRECTLY via g_perm (no gather pass).
// A (!FIRST): Hh in segment order, direct.
// B: native [K][NOUT]; smem tile [64 x 256B], trans ldmatrix.
// FIRST kernel carries an extra z-plane (blockIdx.z == EE) that stream-converts
// W2 fp32->fp16 in GEMM1's wave tail.
static constexpr int BM = 128, BN = 128, BK = 64;
static constexpr int NTHR = 256;
static constexpr int A_T = BM * 128;                    // 16 KB A tile
static constexpr int B_T = BK * 256;                    // 16 KB B tile
static constexpr int STAGE = A_T + B_T;                 // 32 KB
static constexpr int SMEM_GEMM = 3 * STAGE;             // 96 KB -> 2 CTAs/SM

template <int K, int NOUT, bool FIRST>
__global__ void __launch_bounds__(NTHR, 2) gemm_mma(
    const __half* __restrict__ A,
    const __half* __restrict__ B_all,
    const float* __restrict__ ball,
    __half* __restrict__ OutH,
    float* __restrict__ OutF,
    const float* __restrict__ W2src,
    __half* __restrict__ W2dst)
{
    constexpr int KC = K / BK;

    if (FIRST && blockIdx.z == EE) {
        // ---- W2 convert plane: 1024 blocks x 256 thr x 8 iters x 8 elems ----
        int bid = blockIdx.x + (int)gridDim.x * blockIdx.y;   // 0..1023
        size_t base = ((size_t)bid * NTHR + threadIdx.x) * 8;
#pragma unroll
        for (int it = 0; it < 8; it++)
            conv8(W2src, W2dst, base + (size_t)it * ((size_t)1024 * NTHR * 8));
        return;
    }

    int e = blockIdx.z;
    int rowBeg = g_off[e], rowEnd = g_off[e + 1];
    int row0 = rowBeg + blockIdx.y * BM;
    if (row0 >= rowEnd) return;
    int n0 = blockIdx.x * BN;

    const __half* BE = B_all + (size_t)e * K * NOUT;
    const float* bias = ball + (size_t)e * NOUT;

    extern __shared__ __align__(128) char smem[];
    uint32_t sb = smem_u32(smem);

    int tid = threadIdx.x;
    int wid = tid >> 5, lane = tid & 31;
    int warpM = wid & 3, warpN = wid >> 2;              // 4 x 2

    // ---- per-thread gmem->smem geometry (chunk-invariant) ----
    // A tile: 1024 chunks of 16B over [128 rows][8 chunks] -> 4 per thread.
    // Resolve each owned row's base pointer once (indirect for FIRST).
    uint32_t smoA[4];
    const __half* ApB[4];
#pragma unroll
    for (int j = 0; j < 4; j++) {
        int id = tid + j * NTHR;
        int r = id >> 3, c = id & 7;
        smoA[j] = (uint32_t)(r * 128 + ((c ^ (r & 7)) << 4));
        int grow = row0 + r;                 // < TT + PAD by construction
        size_t rowBase;
        if (FIRST) rowBase = (size_t)g_perm[grow] * K;
        else       rowBase = (size_t)grow * K;
        ApB[j] = A + rowBase + c * 8;
    }
    // B tile: 1024 chunks of 16B over [64 rows][16 chunks] -> 4 per thread
    uint32_t smoB[4]; int rkB[4];
#pragma unroll
    for (int j = 0; j < 4; j++) {
        int id = tid + j * NTHR;
        int r = id >> 4, c = id & 15;
        smoB[j] = (uint32_t)(r * 256 + ((c ^ (r & 7)) << 4));
        rkB[j] = r * NOUT + c * 8;
    }

    // ---- ldmatrix per-thread geometry ----
    int rA  = warpM * 32 + (lane & 15);
    int cxA = lane >> 4;
    int sAx = rA & 7;
    // B (trans): lanes 0-7 k0-7, 8-15 k8-15, 16-23 k0-7(+n8), 24-31 k8-15(+n8)
    int bRow = (lane & 7) + (((lane >> 3) & 1) << 3);   // 0..15
    uint32_t bByte = (uint32_t)bRow * 256;
    int c16b = warpN * 8 + (lane >> 4);                 // +2*j per n16-tile
    int sBx = lane & 7;

    float acc[2][8][4];
#pragma unroll
    for (int i = 0; i < 2; i++)
#pragma unroll
        for (int j = 0; j < 8; j++)
#pragma unroll
            for (int q = 0; q < 4; q++) acc[i][j][q] = 0.f;

    // full-chunk issue (prologue only)
    auto issue = [&](int cn) {
        if (cn < KC) {
            int kk = cn * BK;
            uint32_t st = sb + (uint32_t)((cn % 3) * STAGE);
            const __half* Bp = BE + (size_t)kk * NOUT + n0;
#pragma unroll
            for (int j = 0; j < 4; j++) cp16(st + smoA[j], ApB[j] + kk);
#pragma unroll
            for (int j = 0; j < 4; j++) cp16(st + A_T + smoB[j], Bp + rkB[j]);
        }
        cp_commit();
    };

    issue(0); issue(1);

    for (int c = 0; c < KC; c++) {
        cp_wait1();                    // stage c complete (c+1 may be pending)
        __syncthreads();               // all warps done with stage c-1
        // prefetch target for chunk c+2 (interleaved below, committed at end)
        int cn = c + 2;
        bool doPf = cn < KC;
        int kkPf = cn * BK;
        uint32_t stPf = sb + (uint32_t)((cn % 3) * STAGE);
        const __half* BpPf = BE + (size_t)kkPf * NOUT + n0;

        uint32_t st = sb + (uint32_t)((c % 3) * STAGE);
        uint32_t aSm = st, bSm = st + A_T;
#pragma unroll
        for (int ks = 0; ks < 4; ks++) {
            uint32_t aro = (uint32_t)((((ks << 1) + cxA) ^ sAx) << 4);
            uint32_t af[2][4];
#pragma unroll
            for (int i = 0; i < 2; i++) {
                uint32_t roff = (uint32_t)((rA + i * 16) * 128) + aro;
                LDSM4(af[i][0], af[i][1], af[i][2], af[i][3], aSm + roff);
            }
            uint32_t bf[4][4];
            uint32_t bks = bSm + (uint32_t)(ks * 4096) + bByte;
#pragma unroll
            for (int j = 0; j < 4; j++) {
                uint32_t addr = bks + (uint32_t)(((c16b + 2 * j) ^ sBx) << 4);
                LDSM4T(bf[j][0], bf[j][1], bf[j][2], bf[j][3], addr);
            }
            if (doPf) {                // 2 prefetch cp.asyncs per ks
                cp16(stPf + smoA[ks], ApB[ks] + kkPf);
                cp16(stPf + A_T + smoB[ks], BpPf + rkB[ks]);
            }
#pragma unroll
            for (int i = 0; i < 2; i++)
#pragma unroll
                for (int j = 0; j < 4; j++) {
                    MMA16816(acc[i][2 * j],     af[i], bf[j][0], bf[j][1]);
                    MMA16816(acc[i][2 * j + 1], af[i], bf[j][2], bf[j][3]);
                }
        }
        cp_commit();                   // one group per chunk (uniform count)
    }

    // ---- epilogue ----
    int mb = row0 + warpM * 32;
    int nb = n0 + warpN * 64;
    int lr = lane >> 2, lc = (lane & 3) * 2;
    float2 blv[8];
#pragma unroll
    for (int j = 0; j < 8; j++) {
        int col = nb + j * 8 + lc;
        blv[j].x = __ldg(bias + col);
        blv[j].y = __ldg(bias + col + 1);
    }
#pragma unroll
    for (int i = 0; i < 2; i++) {
#pragma unroll
        for (int h = 0; h < 2; h++) {
            int row = mb + i * 16 + lr + h * 8;
            if (row < rowEnd) {
                if (FIRST) {
                    uint32_t* dh = (uint32_t*)(OutH + (size_t)row * NOUT);
#pragma unroll
                    for (int j = 0; j < 8; j++) {
                        int col = nb + j * 8 + lc;
                        float v0 = acc[i][j][2 * h]     + blv[j].x;
                        float v1 = acc[i][j][2 * h + 1] + blv[j].y;
                        v0 = fmaxf(v0, 0.f); v1 = fmaxf(v1, 0.f);
                        __half2 hh;
                        hh.x = __float2half_rn(v0); hh.y = __float2half_rn(v1);
                        dh[col >> 1] = *(uint32_t*)&hh;
                    }
                } else {
                    int tok = g_perm[row];
                    float p = g_prob[tok];
                    float2* dst = (float2*)(OutF + (size_t)tok * NOUT);
#pragma unroll
                    for (int j = 0; j < 8; j++) {
                        int col = nb + j * 8 + lc;
                        float2 o;
                        o.x = (acc[i][j][2 * h]     + blv[j].x) * p;
                        o.y = (acc[i][j][2 * h + 1] + blv[j].y) * p;
                        dst[col >> 1] = o;
                    }
                }
            }
        }
    }
}

// ---------------- entry ----------------
extern "C" void kernel_launch(void* const* d_in, const int* in_sizes, int n_in,
                              void* d_out, int out_size) {
    const float* x  = (const float*)d_in[0];
    const float* Wr = (const float*)d_in[1];
    const float* br = (const float*)d_in[2];
    const float* W1 = (const float*)d_in[3];
    const float* b1 = (const float*)d_in[4];
    const float* W2 = (const float*)d_in[5];
    const float* b2 = (const float*)d_in[6];
    float* out = (float*)d_out;

    __half *Xh, *Hh, *W1h, *W2h;
    cudaGetSymbolAddress((void**)&Xh, g_Xh);
    cudaGetSymbolAddress((void**)&Hh, g_Hh);
    cudaGetSymbolAddress((void**)&W1h, g_W1h);
    cudaGetSymbolAddress((void**)&W2h, g_W2h);

    cudaFuncSetAttribute(gemm_mma<DD, HH, true>,  cudaFuncAttributeMaxDynamicSharedMemorySize, SMEM_GEMM);
    cudaFuncSetAttribute(gemm_mma<HH, DD, false>, cudaFuncAttributeMaxDynamicSharedMemorySize, SMEM_GEMM);

    // router (512 blocks, emits Xh) + W1-convert (1024 blocks): one launch
    router_wconv_kernel<<<TT / 16 + 1024, 512>>>(x, Wr, br, W1, Xh, W1h);
    scan_perm_kernel<<<1, 1024>>>();

    // GEMM1 (perm-indirect A) + trailing W2-convert plane (z == EE)
    dim3 g1(HH / BN, TT / BM, EE + 1);
    gemm_mma<DD, HH, true><<<g1, NTHR, SMEM_GEMM>>>(Xh, W1h, b1, Hh, nullptr, W2, W2h);
    dim3 g2(DD / BN, TT / BM, EE);
    gemm_mma<HH, DD, false><<<g2, NTHR, SMEM_GEMM>>>(Hh, W2h, b2, nullptr, out, nullptr, nullptr);
}